// round 15
// baseline (speedup 1.0000x reference)
#include <cuda_runtime.h>
#include <cuda_bf16.h>
#include <cstdint>
#include <math.h>

// ---------------- problem constants ----------------
#define B_   16
#define S_   512
#define HID_ 768
#define NH_  4
#define HD_  192
#define NL_  9
#define M_ROWS (B_ * S_)   // 8192
#define BH_ (B_ * NH_)     // 64
#define INV_SQRT_D 0.07216878364870323f

// exp(-0.1*k), k=0..5 (dist is integer and clamped)
#define RT0 1.0f
#define RT1 0.9048374180359595f
#define RT2 0.8187307530779818f
#define RT3 0.7408182206817179f
#define RT4 0.6703200460356393f
#define RT5 0.6065306597126334f
__device__ __forceinline__ float rel_tab(int d) {
    return d >= 5 ? RT5 : (d == 0 ? RT0 : d == 1 ? RT1 : d == 2 ? RT2 : d == 3 ? RT3 : RT4);
}

// ---------------- mma / cp.async helpers (sm_80-compatible PTX) ----------------
__device__ __forceinline__ uint32_t smem_to_u32(const void* p) {
    uint32_t a;
    asm("{ .reg .u64 t; cvta.to.shared.u64 t, %1; cvt.u32.u64 %0, t; }" : "=r"(a) : "l"(p));
    return a;
}
__device__ __forceinline__ void ldsm_x4(uint32_t* r, uint32_t addr) {
    asm volatile("ldmatrix.sync.aligned.m8n8.x4.shared.b16 {%0,%1,%2,%3}, [%4];"
        : "=r"(r[0]), "=r"(r[1]), "=r"(r[2]), "=r"(r[3]) : "r"(addr));
}
__device__ __forceinline__ void ldsm_x4_t(uint32_t* r, uint32_t addr) {
    asm volatile("ldmatrix.sync.aligned.m8n8.x4.trans.shared.b16 {%0,%1,%2,%3}, [%4];"
        : "=r"(r[0]), "=r"(r[1]), "=r"(r[2]), "=r"(r[3]) : "r"(addr));
}
__device__ __forceinline__ void mma16816(float* d, const uint32_t* a, const uint32_t* b) {
    asm volatile("mma.sync.aligned.m16n8k16.row.col.f32.bf16.bf16.f32 "
        "{%0,%1,%2,%3}, {%4,%5,%6,%7}, {%8,%9}, {%0,%1,%2,%3};"
        : "+f"(d[0]), "+f"(d[1]), "+f"(d[2]), "+f"(d[3])
        : "r"(a[0]), "r"(a[1]), "r"(a[2]), "r"(a[3]), "r"(b[0]), "r"(b[1]));
}
__device__ __forceinline__ void cp16(uint32_t saddr, const void* g) {
    asm volatile("cp.async.cg.shared.global [%0], [%1], 16;" :: "r"(saddr), "l"(g));
}
#define CP_COMMIT() asm volatile("cp.async.commit_group;" ::: "memory")
#define CP_WAIT1()  asm volatile("cp.async.wait_group 1;" ::: "memory")

// 64-byte rows (4 x 16B chunks)
__device__ __forceinline__ uint32_t sw64(int row, int c16) {
    return (uint32_t)(row * 64 + ((c16 ^ ((row >> 1) & 3)) << 4));
}
// 384-byte rows (24 x 16B chunks): xor low 3 bits of chunk with row&7
__device__ __forceinline__ uint32_t sw384(int row, int c16) {
    return (uint32_t)(row * 384 + ((c16 ^ (row & 7)) << 4));
}

// ---------------- device scratch ----------------
__device__ __nv_bfloat16 g_xhi[M_ROWS * HID_];
__device__ __nv_bfloat16 g_wqkvThi[3 * HID_ * HID_];
__device__ __nv_bfloat16 g_woThi[HID_ * HID_];
__device__ __nv_bfloat16 g_qhi[M_ROWS * HID_];
__device__ __nv_bfloat16 g_khi[M_ROWS * HID_];
__device__ __nv_bfloat16 g_vhi[M_ROWS * HID_];                       // natural [s][d]
__device__ __nv_bfloat16 g_chi[M_ROWS * HID_];
__device__ float         g_h[M_ROWS * HID_];
__device__ float         g_logits[M_ROWS * NL_];

__device__ __forceinline__ uint32_t pack_bf2(float a, float b) {
    __nv_bfloat162 t(__float2bfloat16(a), __float2bfloat16(b));
    return *(uint32_t*)&t;
}

// ---------------- input conversion kernels ----------------
__global__ __launch_bounds__(256) void round4_kernel(
    const float* __restrict__ src, __nv_bfloat16* __restrict__ hi, int n4)
{
    int i = blockIdx.x * 256 + threadIdx.x;
    if (i >= n4) return;
    float4 v = ((const float4*)src)[i];
    __nv_bfloat162 a(__float2bfloat16(v.x), __float2bfloat16(v.y));
    __nv_bfloat162 b(__float2bfloat16(v.z), __float2bfloat16(v.w));
    *(__nv_bfloat162*)(hi + i * 4)     = a;
    *(__nv_bfloat162*)(hi + i * 4 + 2) = b;
}

// weight transpose: z in {0,1,2} -> qkvT, z==3 -> woT (all bf16 hi only)
__global__ void wtrans_kernel(const float* __restrict__ Wq, const float* __restrict__ Wk,
                              const float* __restrict__ Wv, const float* __restrict__ Wo)
{
    __shared__ float tl[32][33];
    const int z = blockIdx.z;
    const float* W = (z == 0) ? Wq : (z == 1) ? Wk : (z == 2) ? Wv : Wo;
    const int n0 = blockIdx.x * 32, k0 = blockIdx.y * 32;
    const int tx = threadIdx.x, ty = threadIdx.y;  // (32,8)
    #pragma unroll
    for (int i = 0; i < 4; i++) {
        int k = ty + i * 8;
        tl[k][tx] = W[(size_t)(k0 + k) * HID_ + n0 + tx];
    }
    __syncthreads();
    #pragma unroll
    for (int i = 0; i < 4; i++) {
        int nloc = ty + i * 8;
        float v = tl[tx][nloc];
        if (z < 3) {
            size_t o = (size_t)(z * HID_ + n0 + nloc) * HID_ + k0 + tx;
            g_wqkvThi[o] = __float2bfloat16(v);
        } else {
            size_t o = (size_t)(n0 + nloc) * HID_ + k0 + tx;
            g_woThi[o] = __float2bfloat16(v);
        }
    }
}

// ---------------- stage loader: A 256x32, B 128x32, 256 threads --------------
__device__ __forceinline__ void stage_load_g(
    uint32_t sstage,
    const __nv_bfloat16* Ah, const __nv_bfloat16* Bh,
    int lda, int ldb, int tid)
{
    // A: 256 rows, 1 row per thread, 4 chunks
    {
        const int row = tid;
        const size_t go = (size_t)row * lda;
        #pragma unroll
        for (int c = 0; c < 4; c++)
            cp16(sstage + sw64(row, c), Ah + go + c * 8);
    }
    // B: 128 rows, 2 threads per row, 2 chunks each (offset 16384)
    {
        const int row = tid >> 1;
        const int c0  = (tid & 1) * 2;
        const size_t go = (size_t)row * ldb + c0 * 8;
        cp16(sstage + 16384 + sw64(row, c0),     Bh + go);
        cp16(sstage + 16384 + sw64(row, c0 + 1), Bh + go + 8);
    }
}

// ---------------- 1-pass bf16 mma.sync GEMM (NT), k-chunk 32, 3-stage -------
// Block 256x128, 8 warps 4x2, warp tile 64x64 (4 mma/ldsm), 256 threads.
// MODE 0: QKV -> q/k/v bf16 (bias fused)   MODE 1: O proj -> fp32 (bias+resid)
template<int MODE>
__global__ __launch_bounds__(256, 1) void mma_gemm(
    const __nv_bfloat16* __restrict__ Ahi, int lda,
    const __nv_bfloat16* __restrict__ Bhi, int ldb,
    float* __restrict__ C, int ldc, int K,
    const float* __restrict__ bb0, const float* __restrict__ bb1,
    const float* __restrict__ bb2, const float* __restrict__ resid)
{
    constexpr int ATSZ  = 256 * 64;     // 16384
    constexpr int BTSZ  = 128 * 64;     // 8192
    constexpr int STAGE = ATSZ + BTSZ;  // 24576

    extern __shared__ char smem[];
    const uint32_t sbase = smem_to_u32(smem);
    const int tid  = threadIdx.x;
    const int lane = tid & 31;
    const int wid  = tid >> 5;
    const int wm   = (wid >> 1) * 64;   // 4 warp-rows
    const int wn   = (wid & 1) * 64;    // 2 warp-cols

    const int bm = blockIdx.y * 256;
    const int bn = blockIdx.x * 128;

    const __nv_bfloat16* Ah = Ahi + (size_t)bm * lda;
    const __nv_bfloat16* Bh = Bhi + (size_t)bn * ldb;

    float acc[4][8][4];
    #pragma unroll
    for (int i = 0; i < 4; i++)
        #pragma unroll
        for (int j = 0; j < 8; j++)
            #pragma unroll
            for (int u = 0; u < 4; u++) acc[i][j][u] = 0.f;

    const int nt = K >> 5;

    stage_load_g(sbase, Ah, Bh, lda, ldb, tid);
    CP_COMMIT();
    stage_load_g(sbase + STAGE, Ah + 32, Bh + 32, lda, ldb, tid);
    CP_COMMIT();

    for (int t = 0; t < nt; ++t) {
        CP_WAIT1();
        __syncthreads();

        {
            const uint32_t aB = sbase + (t % 3) * STAGE;
            const uint32_t bB = aB + ATSZ;
            #pragma unroll
            for (int ks = 0; ks < 2; ++ks) {
                uint32_t ah[4][4];
                const int arow0 = wm + (lane & 15);
                const int ac16  = ks * 2 + (lane >> 4);
                #pragma unroll
                for (int im = 0; im < 4; im++)
                    ldsm_x4(ah[im], aB + sw64(arow0 + im * 16, ac16));
                uint32_t bhf[4][4];
                const int brow0 = wn + (lane & 7) + ((lane >> 4) << 3);
                const int bc16  = ks * 2 + ((lane >> 3) & 1);
                #pragma unroll
                for (int ib = 0; ib < 4; ib++)
                    ldsm_x4(bhf[ib], bB + sw64(brow0 + ib * 16, bc16));
                #pragma unroll
                for (int im = 0; im < 4; im++)
                    #pragma unroll
                    for (int in = 0; in < 8; in++)
                        mma16816(acc[im][in], ah[im], &bhf[in >> 1][(in & 1) * 2]);
            }
        }

        if (t + 2 < nt) {
            stage_load_g(sbase + ((t + 2) % 3) * STAGE,
                         Ah + (t + 2) * 32, Bh + (t + 2) * 32, lda, ldb, tid);
        }
        CP_COMMIT();
    }

    // ---- epilogue ----
    #pragma unroll
    for (int im = 0; im < 4; im++) {
        #pragma unroll
        for (int in = 0; in < 8; in++) {
            const int gm0 = bm + wm + im * 16 + (lane >> 2);
            const int n   = bn + wn + in * 8 + ((lane & 3) << 1);
            float* d = acc[im][in];
            if (MODE == 0) {
                #pragma unroll
                for (int half = 0; half < 2; half++) {
                    int gm = gm0 + half * 8;
                    float v0 = d[half * 2 + 0];
                    float v1 = d[half * 2 + 1];
                    int seg = (n >= 1536) ? 2 : (n >= 768) ? 1 : 0;
                    int col = n - seg * 768;
                    const float* bias = (seg == 0) ? bb0 : (seg == 1) ? bb1 : bb2;
                    v0 += bias[col];
                    v1 += bias[col + 1];
                    size_t o = (size_t)gm * HID_ + col;
                    __nv_bfloat16* dh = (seg == 0) ? &g_qhi[o] : (seg == 1) ? &g_khi[o] : &g_vhi[o];
                    *(__nv_bfloat162*)dh = __nv_bfloat162(__float2bfloat16(v0), __float2bfloat16(v1));
                }
            } else {
                #pragma unroll
                for (int half = 0; half < 2; half++) {
                    int gm = gm0 + half * 8;
                    float2 o;
                    o.x = d[half * 2 + 0] + bb0[n]     + resid[(size_t)gm * HID_ + n];
                    o.y = d[half * 2 + 1] + bb0[n + 1] + resid[(size_t)gm * HID_ + n + 1];
                    *(float2*)(C + (size_t)gm * ldc + n) = o;
                }
            }
        }
    }
}

// ---------------- fused flash attention (champion config, unchanged) --------
#define FA_QSZ   49152                    // 128 x 384B
#define FA_KVSZ  24576                    // 64 x 384B
#define FA_STAGE (2 * FA_KVSZ)            // K + V
__global__ __launch_bounds__(256, 1) void flash_attn()
{
    extern __shared__ char smem[];
    const uint32_t sbase = smem_to_u32(smem);
    const uint32_t Qs = sbase;

    const int tid  = threadIdx.x;
    const int lane = tid & 31;
    const int w    = tid >> 5;

    const int qt = blockIdx.x;
    const int bh = blockIdx.y;
    const int b = bh >> 2, h = bh & 3;

    const __nv_bfloat16* Qg = g_qhi + ((size_t)(b * S_ + qt * 128)) * HID_ + h * HD_;
    const __nv_bfloat16* Kg = g_khi + ((size_t)(b * S_)) * HID_ + h * HD_;
    const __nv_bfloat16* Vg = g_vhi + ((size_t)(b * S_)) * HID_ + h * HD_;

    {
        const int row = tid >> 1;
        const int c0  = (tid & 1) * 12;
        #pragma unroll
        for (int j = 0; j < 12; j++)
            cp16(Qs + sw384(row, c0 + j), Qg + (size_t)row * HID_ + (c0 + j) * 8);
    }

    #define FA_LOAD(KT, STG) do { \
        uint32_t sb_ = sbase + FA_QSZ + (STG) * FA_STAGE; \
        const int row_ = tid >> 2; \
        const int c0_  = (tid & 3) * 6; \
        const __nv_bfloat16* Kp = Kg + (size_t)((KT) * 64 + row_) * HID_; \
        const __nv_bfloat16* Vp = Vg + (size_t)((KT) * 64 + row_) * HID_; \
        _Pragma("unroll") \
        for (int j_ = 0; j_ < 6; j_++) { \
            uint32_t so_ = sw384(row_, c0_ + j_); \
            cp16(sb_ + so_,           Kp + (c0_ + j_) * 8); \
            cp16(sb_ + FA_KVSZ + so_, Vp + (c0_ + j_) * 8); \
        } \
    } while (0)

    FA_LOAD(0, 0); CP_COMMIT();
    FA_LOAD(1, 1); CP_COMMIT();

    float acc_o[24][4];
    #pragma unroll
    for (int i = 0; i < 24; i++)
        #pragma unroll
        for (int u = 0; u < 4; u++) acc_o[i][u] = 0.f;
    float m0 = -1e30f, m1 = -1e30f, l0 = 0.f, l1 = 0.f;

    const int qrow0 = qt * 128 + w * 16 + (lane >> 2);
    const int qcol0 = (lane & 3) << 1;

    for (int kt = 0; kt < 8; ++kt) {
        CP_WAIT1();
        __syncthreads();

        if (kt + 2 < 8) FA_LOAD(kt + 2, (kt + 2) % 3);
        CP_COMMIT();

        const uint32_t Ks = sbase + FA_QSZ + (kt % 3) * FA_STAGE;
        const uint32_t Vs = Ks + FA_KVSZ;

        float s[8][4];
        #pragma unroll
        for (int j = 0; j < 8; j++)
            #pragma unroll
            for (int u = 0; u < 4; u++) s[j][u] = 0.f;

        #pragma unroll
        for (int kc = 0; kc < 12; ++kc) {
            uint32_t aq[4];
            ldsm_x4(aq, Qs + sw384(w * 16 + (lane & 15), kc * 2 + (lane >> 4)));
            #pragma unroll
            for (int g = 0; g < 4; g++) {
                uint32_t bk[4];
                ldsm_x4(bk, Ks + sw384(g * 16 + (lane & 7) + ((lane >> 4) << 3),
                                       kc * 2 + ((lane >> 3) & 1)));
                mma16816(s[2 * g],     aq, &bk[0]);
                mma16816(s[2 * g + 1], aq, &bk[2]);
            }
        }

        float mn0 = m0, mn1 = m1;
        #pragma unroll
        for (int j = 0; j < 8; j++) {
            const int kc0 = kt * 64 + j * 8 + qcol0;
            int da = qrow0 - kc0;        da = da < 0 ? -da : da;
            int db = qrow0 - (kc0 + 1);  db = db < 0 ? -db : db;
            int dc = qrow0 + 8 - kc0;    dc = dc < 0 ? -dc : dc;
            int dd = qrow0 + 8 - (kc0 + 1); dd = dd < 0 ? -dd : dd;
            s[j][0] = (s[j][0] + rel_tab(da)) * INV_SQRT_D - 0.1f * (float)da;
            s[j][1] = (s[j][1] + rel_tab(db)) * INV_SQRT_D - 0.1f * (float)db;
            s[j][2] = (s[j][2] + rel_tab(dc)) * INV_SQRT_D - 0.1f * (float)dc;
            s[j][3] = (s[j][3] + rel_tab(dd)) * INV_SQRT_D - 0.1f * (float)dd;
            mn0 = fmaxf(mn0, fmaxf(s[j][0], s[j][1]));
            mn1 = fmaxf(mn1, fmaxf(s[j][2], s[j][3]));
        }
        mn0 = fmaxf(mn0, __shfl_xor_sync(0xffffffffu, mn0, 1));
        mn0 = fmaxf(mn0, __shfl_xor_sync(0xffffffffu, mn0, 2));
        mn1 = fmaxf(mn1, __shfl_xor_sync(0xffffffffu, mn1, 1));
        mn1 = fmaxf(mn1, __shfl_xor_sync(0xffffffffu, mn1, 2));

        const float alpha0 = __expf(m0 - mn0);
        const float alpha1 = __expf(m1 - mn1);
        m0 = mn0; m1 = mn1;

        float sum0 = 0.f, sum1 = 0.f;
        #pragma unroll
        for (int j = 0; j < 8; j++) {
            s[j][0] = __expf(s[j][0] - mn0);
            s[j][1] = __expf(s[j][1] - mn0);
            s[j][2] = __expf(s[j][2] - mn1);
            s[j][3] = __expf(s[j][3] - mn1);
            sum0 += s[j][0] + s[j][1];
            sum1 += s[j][2] + s[j][3];
        }
        sum0 += __shfl_xor_sync(0xffffffffu, sum0, 1);
        sum0 += __shfl_xor_sync(0xffffffffu, sum0, 2);
        sum1 += __shfl_xor_sync(0xffffffffu, sum1, 1);
        sum1 += __shfl_xor_sync(0xffffffffu, sum1, 2);
        l0 = l0 * alpha0 + sum0;
        l1 = l1 * alpha1 + sum1;

        #pragma unroll
        for (int i = 0; i < 24; i++) {
            acc_o[i][0] *= alpha0; acc_o[i][1] *= alpha0;
            acc_o[i][2] *= alpha1; acc_o[i][3] *= alpha1;
        }

        #pragma unroll
        for (int kc2 = 0; kc2 < 4; ++kc2) {
            uint32_t af[4];
            af[0] = pack_bf2(s[2 * kc2][0],     s[2 * kc2][1]);
            af[1] = pack_bf2(s[2 * kc2][2],     s[2 * kc2][3]);
            af[2] = pack_bf2(s[2 * kc2 + 1][0], s[2 * kc2 + 1][1]);
            af[3] = pack_bf2(s[2 * kc2 + 1][2], s[2 * kc2 + 1][3]);
            const int krow = kc2 * 16 + (lane & 7) + (((lane >> 3) & 1) << 3);
            #pragma unroll
            for (int g = 0; g < 12; g++) {
                uint32_t bv[4];
                ldsm_x4_t(bv, Vs + sw384(krow, g * 2 + (lane >> 4)));
                mma16816(acc_o[2 * g],     af, &bv[0]);
                mma16816(acc_o[2 * g + 1], af, &bv[2]);
            }
        }
    }

    const float inv0 = 1.0f / l0;
    const float inv1 = 1.0f / l1;
    const size_t coff = ((size_t)(b * S_ + qt * 128 + w * 16 + (lane >> 2))) * HID_ + h * HD_;
    #pragma unroll
    for (int i = 0; i < 24; i++) {
        const int d = i * 8 + qcol0;
        *(uint32_t*)&g_chi[coff + d] = pack_bf2(acc_o[i][0] * inv0, acc_o[i][1] * inv0);
        *(uint32_t*)&g_chi[coff + 8 * HID_ + d] = pack_bf2(acc_o[i][2] * inv1, acc_o[i][3] * inv1);
    }
    #undef FA_LOAD
}

// ---------------- fused LayerNorm + classifier ----------------
__global__ __launch_bounds__(288) void ln_cls_kernel(
    const float* __restrict__ lng, const float* __restrict__ lnb,
    const float* __restrict__ Ws, const float* __restrict__ bs)
{
    __shared__ float sh[HID_];
    __shared__ float red[288];
    const int row = blockIdx.x;
    const float* p = g_h + (size_t)row * HID_;
    const int tid = threadIdx.x;

    float ssum = 0.f;
    for (int i = tid; i < HID_; i += 288) {
        float v = p[i];
        sh[i] = v;
        ssum += v;
    }
    red[tid] = ssum;
    __syncthreads();
    if (tid < 32) red[tid] += red[tid + 256];
    __syncthreads();
    for (int off = 128; off > 0; off >>= 1) {
        if (tid < off) red[tid] += red[tid + off];
        __syncthreads();
    }
    const float mu = red[0] * (1.0f / HID_);
    __syncthreads();

    float sq = 0.f;
    for (int i = tid; i < HID_; i += 288) {
        float d = sh[i] - mu;
        sq += d * d;
    }
    red[tid] = sq;
    __syncthreads();
    if (tid < 32) red[tid] += red[tid + 256];
    __syncthreads();
    for (int off = 128; off > 0; off >>= 1) {
        if (tid < off) red[tid] += red[tid + off];
        __syncthreads();
    }
    const float rstd = rsqrtf(red[0] * (1.0f / HID_) + 1e-5f);
    __syncthreads();

    for (int i = tid; i < HID_; i += 288)
        sh[i] = (sh[i] - mu) * rstd * lng[i] + lnb[i];
    __syncthreads();

    const int w = tid >> 5;
    const int lane = tid & 31;
    float a = 0.f;
    for (int d = lane; d < HID_; d += 32)
        a = fmaf(sh[d], Ws[d * NL_ + w], a);
    #pragma unroll
    for (int off = 16; off > 0; off >>= 1)
        a += __shfl_down_sync(0xffffffffu, a, off);
    if (lane == 0)
        g_logits[(size_t)row * NL_ + w] = a + bs[w];
}

// ---------------- entity-bias bump + final write ----------------
__global__ __launch_bounds__(256) void bump_kernel(
    const float* __restrict__ eb, float* __restrict__ out)
{
    int row = blockIdx.x * 256 + threadIdx.x;
    if (row >= M_ROWS) return;
    float add = 0.f;
    if (row & (S_ - 1)) {
        const float* lp = g_logits + (size_t)(row - 1) * NL_;
        int am = 0; float best = lp[0];
        #pragma unroll
        for (int l = 1; l < NL_; l++)
            if (lp[l] > best) { best = lp[l]; am = l; }
        if (am == 1) add = 2.0f * eb[2];
    }
    const float* lc = g_logits + (size_t)row * NL_;
    #pragma unroll
    for (int l = 0; l < NL_; l++)
        out[(size_t)row * NL_ + l] = lc[l] + ((l == 2) ? add : 0.f);
}

// ---------------- launch ----------------
extern "C" void kernel_launch(void* const* d_in, const int* in_sizes, int n_in,
                              void* d_out, int out_size)
{
    const float* x   = (const float*)d_in[0];
    const float* Wq  = (const float*)d_in[1];
    const float* bq  = (const float*)d_in[2];
    const float* Wk  = (const float*)d_in[3];
    const float* bk  = (const float*)d_in[4];
    const float* Wv  = (const float*)d_in[5];
    const float* bv  = (const float*)d_in[6];
    const float* Wo  = (const float*)d_in[7];
    const float* bo  = (const float*)d_in[8];
    const float* lng = (const float*)d_in[9];
    const float* lnb = (const float*)d_in[10];
    const float* Ws  = (const float*)d_in[11];
    const float* bs  = (const float*)d_in[12];
    const float* eb  = (const float*)d_in[13];
    float* out = (float*)d_out;

    __nv_bfloat16 *xhi, *wqkvThi, *woThi, *chi;
    float *gh;
    cudaGetSymbolAddress((void**)&xhi, g_xhi);
    cudaGetSymbolAddress((void**)&wqkvThi, g_wqkvThi);
    cudaGetSymbolAddress((void**)&woThi, g_woThi);
    cudaGetSymbolAddress((void**)&chi, g_chi);
    cudaGetSymbolAddress((void**)&gh, g_h);

    const int SMEM_G  = 3 * 24576;                // 73728
    const int SMEM_FA = FA_QSZ + 3 * FA_STAGE;    // 196608
    cudaFuncSetAttribute(mma_gemm<0>, cudaFuncAttributeMaxDynamicSharedMemorySize, SMEM_G);
    cudaFuncSetAttribute(mma_gemm<1>, cudaFuncAttributeMaxDynamicSharedMemorySize, SMEM_G);
    cudaFuncSetAttribute(flash_attn,  cudaFuncAttributeMaxDynamicSharedMemorySize, SMEM_FA);

    // 1. round x -> bf16
    round4_kernel<<<(M_ROWS * HID_ / 4 + 255) / 256, 256>>>(x, xhi, M_ROWS * HID_ / 4);
    // 2. transpose weights -> bf16
    wtrans_kernel<<<dim3(24, 24, 4), dim3(32, 8)>>>(Wq, Wk, Wv, Wo);
    // 3. QKV projection (1-pass bf16, 256x128 blocks) -> q/k/v bf16
    mma_gemm<0><<<dim3(18, 32, 1), 256, SMEM_G>>>(
        xhi, HID_, wqkvThi, HID_, nullptr, 0, HID_, bq, bk, bv, nullptr);
    // 4. fused attention -> ctx bf16
    flash_attn<<<dim3(4, BH_), 256, SMEM_FA>>>();
    // 5. O projection (1-pass bf16) + bias + fp32 residual -> g_h
    mma_gemm<1><<<dim3(6, 32, 1), 256, SMEM_G>>>(
        chi, HID_, woThi, HID_, gh, HID_, HID_, bo, nullptr, nullptr, x);
    // 6. fused layernorm + classifier -> g_logits
    ln_cls_kernel<<<M_ROWS, 288>>>(lng, lnb, Ws, bs);
    // 7. entity bump + final write
    bump_kernel<<<(M_ROWS + 255) / 256, 256>>>(eb, out);
}

// round 16
// speedup vs baseline: 1.2519x; 1.2519x over previous
#include <cuda_runtime.h>
#include <cuda_bf16.h>
#include <cstdint>
#include <math.h>

// ---------------- problem constants ----------------
#define B_   16
#define S_   512
#define HID_ 768
#define NH_  4
#define HD_  192
#define NL_  9
#define M_ROWS (B_ * S_)   // 8192
#define BH_ (B_ * NH_)     // 64
#define INV_SQRT_D 0.07216878364870323f

// exp(-0.1*k), k=0..5 (dist is integer and clamped)
#define RT0 1.0f
#define RT1 0.9048374180359595f
#define RT2 0.8187307530779818f
#define RT3 0.7408182206817179f
#define RT4 0.6703200460356393f
#define RT5 0.6065306597126334f
__device__ __forceinline__ float rel_tab(int d) {
    return d >= 5 ? RT5 : (d == 0 ? RT0 : d == 1 ? RT1 : d == 2 ? RT2 : d == 3 ? RT3 : RT4);
}

// ---------------- mma / cp.async helpers (sm_80-compatible PTX) ----------------
__device__ __forceinline__ uint32_t smem_to_u32(const void* p) {
    uint32_t a;
    asm("{ .reg .u64 t; cvta.to.shared.u64 t, %1; cvt.u32.u64 %0, t; }" : "=r"(a) : "l"(p));
    return a;
}
__device__ __forceinline__ void ldsm_x4(uint32_t* r, uint32_t addr) {
    asm volatile("ldmatrix.sync.aligned.m8n8.x4.shared.b16 {%0,%1,%2,%3}, [%4];"
        : "=r"(r[0]), "=r"(r[1]), "=r"(r[2]), "=r"(r[3]) : "r"(addr));
}
__device__ __forceinline__ void ldsm_x4_t(uint32_t* r, uint32_t addr) {
    asm volatile("ldmatrix.sync.aligned.m8n8.x4.trans.shared.b16 {%0,%1,%2,%3}, [%4];"
        : "=r"(r[0]), "=r"(r[1]), "=r"(r[2]), "=r"(r[3]) : "r"(addr));
}
__device__ __forceinline__ void mma16816(float* d, const uint32_t* a, const uint32_t* b) {
    asm volatile("mma.sync.aligned.m16n8k16.row.col.f32.bf16.bf16.f32 "
        "{%0,%1,%2,%3}, {%4,%5,%6,%7}, {%8,%9}, {%0,%1,%2,%3};"
        : "+f"(d[0]), "+f"(d[1]), "+f"(d[2]), "+f"(d[3])
        : "r"(a[0]), "r"(a[1]), "r"(a[2]), "r"(a[3]), "r"(b[0]), "r"(b[1]));
}
__device__ __forceinline__ void cp16(uint32_t saddr, const void* g) {
    asm volatile("cp.async.cg.shared.global [%0], [%1], 16;" :: "r"(saddr), "l"(g));
}
#define CP_COMMIT() asm volatile("cp.async.commit_group;" ::: "memory")
#define CP_WAIT1()  asm volatile("cp.async.wait_group 1;" ::: "memory")

// 64-byte rows (4 x 16B chunks)
__device__ __forceinline__ uint32_t sw64(int row, int c16) {
    return (uint32_t)(row * 64 + ((c16 ^ ((row >> 1) & 3)) << 4));
}
// 384-byte rows (24 x 16B chunks): xor low 3 bits of chunk with row&7
__device__ __forceinline__ uint32_t sw384(int row, int c16) {
    return (uint32_t)(row * 384 + ((c16 ^ (row & 7)) << 4));
}

// ---------------- device scratch ----------------
__device__ __nv_bfloat16 g_xhi[M_ROWS * HID_];
__device__ __nv_bfloat16 g_wqkvThi[3 * HID_ * HID_];
__device__ __nv_bfloat16 g_woThi[HID_ * HID_];
__device__ __nv_bfloat16 g_qhi[M_ROWS * HID_];
__device__ __nv_bfloat16 g_khi[M_ROWS * HID_];
__device__ __nv_bfloat16 g_vhi[M_ROWS * HID_];                       // natural [s][d]
__device__ __nv_bfloat16 g_chi[M_ROWS * HID_];
__device__ float         g_h[M_ROWS * HID_];
__device__ float         g_logits[M_ROWS * NL_];

__device__ __forceinline__ uint32_t pack_bf2(float a, float b) {
    __nv_bfloat162 t(__float2bfloat16(a), __float2bfloat16(b));
    return *(uint32_t*)&t;
}

// ---------------- input conversion kernels ----------------
__global__ __launch_bounds__(256) void round4_kernel(
    const float* __restrict__ src, __nv_bfloat16* __restrict__ hi, int n4)
{
    int i = blockIdx.x * 256 + threadIdx.x;
    if (i >= n4) return;
    float4 v = ((const float4*)src)[i];
    __nv_bfloat162 a(__float2bfloat16(v.x), __float2bfloat16(v.y));
    __nv_bfloat162 b(__float2bfloat16(v.z), __float2bfloat16(v.w));
    *(__nv_bfloat162*)(hi + i * 4)     = a;
    *(__nv_bfloat162*)(hi + i * 4 + 2) = b;
}

// weight transpose: z in {0,1,2} -> qkvT, z==3 -> woT (all bf16 hi only)
__global__ void wtrans_kernel(const float* __restrict__ Wq, const float* __restrict__ Wk,
                              const float* __restrict__ Wv, const float* __restrict__ Wo)
{
    __shared__ float tl[32][33];
    const int z = blockIdx.z;
    const float* W = (z == 0) ? Wq : (z == 1) ? Wk : (z == 2) ? Wv : Wo;
    const int n0 = blockIdx.x * 32, k0 = blockIdx.y * 32;
    const int tx = threadIdx.x, ty = threadIdx.y;  // (32,8)
    #pragma unroll
    for (int i = 0; i < 4; i++) {
        int k = ty + i * 8;
        tl[k][tx] = W[(size_t)(k0 + k) * HID_ + n0 + tx];
    }
    __syncthreads();
    #pragma unroll
    for (int i = 0; i < 4; i++) {
        int nloc = ty + i * 8;
        float v = tl[tx][nloc];
        if (z < 3) {
            size_t o = (size_t)(z * HID_ + n0 + nloc) * HID_ + k0 + tx;
            g_wqkvThi[o] = __float2bfloat16(v);
        } else {
            size_t o = (size_t)(n0 + nloc) * HID_ + k0 + tx;
            g_woThi[o] = __float2bfloat16(v);
        }
    }
}

// ---------------- stage loader (cp.async, 64B rows, 256 threads) ----------------
__device__ __forceinline__ void stage_load_g(
    uint32_t sstage,
    const __nv_bfloat16* Ah, const __nv_bfloat16* Bh,
    int lda, int ldb, int tid)
{
    const int row = tid >> 1;
    const int c0  = (tid & 1) * 2;
    const uint32_t s0 = sw64(row, c0);
    const uint32_t s1 = sw64(row, c0 + 1);
    const size_t goA = (size_t)row * lda + c0 * 8;
    const size_t goB = (size_t)row * ldb + c0 * 8;
    cp16(sstage + s0, Ah + goA);
    cp16(sstage + s1, Ah + goA + 8);
    cp16(sstage + 8192 + s0, Bh + goB);
    cp16(sstage + 8192 + s1, Bh + goB + 8);
}

// ---------------- 1-pass bf16 mma.sync GEMM (NT), k-chunk 32, 3-stage -------
// Block 128x128, 8 warps 2x4, warp tile 64x32, 2 CTAs/SM.  (R13 champion)
// MODE 0: QKV -> q/k/v bf16 (bias fused)   MODE 1: O proj -> fp32 (bias+resid)
template<int MODE>
__global__ __launch_bounds__(256, 2) void mma_gemm(
    const __nv_bfloat16* __restrict__ Ahi, int lda,
    const __nv_bfloat16* __restrict__ Bhi, int ldb,
    float* __restrict__ C, int ldc, int K,
    const float* __restrict__ bb0, const float* __restrict__ bb1,
    const float* __restrict__ bb2, const float* __restrict__ resid)
{
    constexpr int TSZ   = 128 * 64;     // 8192
    constexpr int STAGE = 2 * TSZ;      // 16384

    extern __shared__ char smem[];
    const uint32_t sbase = smem_to_u32(smem);
    const int tid  = threadIdx.x;
    const int lane = tid & 31;
    const int wid  = tid >> 5;
    const int wm   = (wid >> 2) * 64;
    const int wn   = (wid & 3) * 32;

    const int bm = blockIdx.y * 128;
    const int bn = blockIdx.x * 128;

    const __nv_bfloat16* Ah = Ahi + (size_t)bm * lda;
    const __nv_bfloat16* Bh = Bhi + (size_t)bn * ldb;

    float acc[4][4][4];
    #pragma unroll
    for (int i = 0; i < 4; i++)
        #pragma unroll
        for (int j = 0; j < 4; j++)
            #pragma unroll
            for (int u = 0; u < 4; u++) acc[i][j][u] = 0.f;

    const int nt = K >> 5;

    stage_load_g(sbase, Ah, Bh, lda, ldb, tid);
    CP_COMMIT();
    stage_load_g(sbase + STAGE, Ah + 32, Bh + 32, lda, ldb, tid);
    CP_COMMIT();

    for (int t = 0; t < nt; ++t) {
        CP_WAIT1();
        __syncthreads();

        {
            const uint32_t aB = sbase + (t % 3) * STAGE;
            const uint32_t bB = aB + TSZ;
            #pragma unroll
            for (int ks = 0; ks < 2; ++ks) {
                uint32_t ah[4][4];
                const int arow0 = wm + (lane & 15);
                const int ac16  = ks * 2 + (lane >> 4);
                #pragma unroll
                for (int im = 0; im < 4; im++)
                    ldsm_x4(ah[im], aB + sw64(arow0 + im * 16, ac16));
                uint32_t bhf[2][4];
                const int brow0 = wn + (lane & 7) + ((lane >> 4) << 3);
                const int bc16  = ks * 2 + ((lane >> 3) & 1);
                #pragma unroll
                for (int ib = 0; ib < 2; ib++)
                    ldsm_x4(bhf[ib], bB + sw64(brow0 + ib * 16, bc16));
                #pragma unroll
                for (int im = 0; im < 4; im++)
                    #pragma unroll
                    for (int in = 0; in < 4; in++)
                        mma16816(acc[im][in], ah[im], &bhf[in >> 1][(in & 1) * 2]);
            }
        }

        if (t + 2 < nt) {
            stage_load_g(sbase + ((t + 2) % 3) * STAGE,
                         Ah + (t + 2) * 32, Bh + (t + 2) * 32, lda, ldb, tid);
        }
        CP_COMMIT();
    }

    // ---- epilogue ----
    #pragma unroll
    for (int im = 0; im < 4; im++) {
        #pragma unroll
        for (int in = 0; in < 4; in++) {
            const int gm0 = bm + wm + im * 16 + (lane >> 2);
            const int n   = bn + wn + in * 8 + ((lane & 3) << 1);
            float* d = acc[im][in];
            if (MODE == 0) {
                #pragma unroll
                for (int half = 0; half < 2; half++) {
                    int gm = gm0 + half * 8;
                    float v0 = d[half * 2 + 0];
                    float v1 = d[half * 2 + 1];
                    int seg = (n >= 1536) ? 2 : (n >= 768) ? 1 : 0;
                    int col = n - seg * 768;
                    const float* bias = (seg == 0) ? bb0 : (seg == 1) ? bb1 : bb2;
                    v0 += bias[col];
                    v1 += bias[col + 1];
                    size_t o = (size_t)gm * HID_ + col;
                    __nv_bfloat16* dh = (seg == 0) ? &g_qhi[o] : (seg == 1) ? &g_khi[o] : &g_vhi[o];
                    *(__nv_bfloat162*)dh = __nv_bfloat162(__float2bfloat16(v0), __float2bfloat16(v1));
                }
            } else {
                #pragma unroll
                for (int half = 0; half < 2; half++) {
                    int gm = gm0 + half * 8;
                    float2 o;
                    o.x = d[half * 2 + 0] + bb0[n]     + resid[(size_t)gm * HID_ + n];
                    o.y = d[half * 2 + 1] + bb0[n + 1] + resid[(size_t)gm * HID_ + n + 1];
                    *(float2*)(C + (size_t)gm * ldc + n) = o;
                }
            }
        }
    }
}

// ---------------- fused flash attention (champion config) ----------------
#define FA_QSZ   49152                    // 128 x 384B
#define FA_KVSZ  24576                    // 64 x 384B
#define FA_STAGE (2 * FA_KVSZ)            // K + V
__global__ __launch_bounds__(256, 1) void flash_attn()
{
    extern __shared__ char smem[];
    const uint32_t sbase = smem_to_u32(smem);
    const uint32_t Qs = sbase;

    const int tid  = threadIdx.x;
    const int lane = tid & 31;
    const int w    = tid >> 5;

    const int qt = blockIdx.x;
    const int bh = blockIdx.y;
    const int b = bh >> 2, h = bh & 3;

    const __nv_bfloat16* Qg = g_qhi + ((size_t)(b * S_ + qt * 128)) * HID_ + h * HD_;
    const __nv_bfloat16* Kg = g_khi + ((size_t)(b * S_)) * HID_ + h * HD_;
    const __nv_bfloat16* Vg = g_vhi + ((size_t)(b * S_)) * HID_ + h * HD_;

    {
        const int row = tid >> 1;
        const int c0  = (tid & 1) * 12;
        #pragma unroll
        for (int j = 0; j < 12; j++)
            cp16(Qs + sw384(row, c0 + j), Qg + (size_t)row * HID_ + (c0 + j) * 8);
    }

    #define FA_LOAD(KT, STG) do { \
        uint32_t sb_ = sbase + FA_QSZ + (STG) * FA_STAGE; \
        const int row_ = tid >> 2; \
        const int c0_  = (tid & 3) * 6; \
        const __nv_bfloat16* Kp = Kg + (size_t)((KT) * 64 + row_) * HID_; \
        const __nv_bfloat16* Vp = Vg + (size_t)((KT) * 64 + row_) * HID_; \
        _Pragma("unroll") \
        for (int j_ = 0; j_ < 6; j_++) { \
            uint32_t so_ = sw384(row_, c0_ + j_); \
            cp16(sb_ + so_,           Kp + (c0_ + j_) * 8); \
            cp16(sb_ + FA_KVSZ + so_, Vp + (c0_ + j_) * 8); \
        } \
    } while (0)

    FA_LOAD(0, 0); CP_COMMIT();
    FA_LOAD(1, 1); CP_COMMIT();

    float acc_o[24][4];
    #pragma unroll
    for (int i = 0; i < 24; i++)
        #pragma unroll
        for (int u = 0; u < 4; u++) acc_o[i][u] = 0.f;
    float m0 = -1e30f, m1 = -1e30f, l0 = 0.f, l1 = 0.f;

    const int qrow0 = qt * 128 + w * 16 + (lane >> 2);
    const int qcol0 = (lane & 3) << 1;

    for (int kt = 0; kt < 8; ++kt) {
        CP_WAIT1();
        __syncthreads();

        if (kt + 2 < 8) FA_LOAD(kt + 2, (kt + 2) % 3);
        CP_COMMIT();

        const uint32_t Ks = sbase + FA_QSZ + (kt % 3) * FA_STAGE;
        const uint32_t Vs = Ks + FA_KVSZ;

        float s[8][4];
        #pragma unroll
        for (int j = 0; j < 8; j++)
            #pragma unroll
            for (int u = 0; u < 4; u++) s[j][u] = 0.f;

        #pragma unroll
        for (int kc = 0; kc < 12; ++kc) {
            uint32_t aq[4];
            ldsm_x4(aq, Qs + sw384(w * 16 + (lane & 15), kc * 2 + (lane >> 4)));
            #pragma unroll
            for (int g = 0; g < 4; g++) {
                uint32_t bk[4];
                ldsm_x4(bk, Ks + sw384(g * 16 + (lane & 7) + ((lane >> 4) << 3),
                                       kc * 2 + ((lane >> 3) & 1)));
                mma16816(s[2 * g],     aq, &bk[0]);
                mma16816(s[2 * g + 1], aq, &bk[2]);
            }
        }

        float mn0 = m0, mn1 = m1;
        #pragma unroll
        for (int j = 0; j < 8; j++) {
            const int kc0 = kt * 64 + j * 8 + qcol0;
            int da = qrow0 - kc0;        da = da < 0 ? -da : da;
            int db = qrow0 - (kc0 + 1);  db = db < 0 ? -db : db;
            int dc = qrow0 + 8 - kc0;    dc = dc < 0 ? -dc : dc;
            int dd = qrow0 + 8 - (kc0 + 1); dd = dd < 0 ? -dd : dd;
            s[j][0] = (s[j][0] + rel_tab(da)) * INV_SQRT_D - 0.1f * (float)da;
            s[j][1] = (s[j][1] + rel_tab(db)) * INV_SQRT_D - 0.1f * (float)db;
            s[j][2] = (s[j][2] + rel_tab(dc)) * INV_SQRT_D - 0.1f * (float)dc;
            s[j][3] = (s[j][3] + rel_tab(dd)) * INV_SQRT_D - 0.1f * (float)dd;
            mn0 = fmaxf(mn0, fmaxf(s[j][0], s[j][1]));
            mn1 = fmaxf(mn1, fmaxf(s[j][2], s[j][3]));
        }
        mn0 = fmaxf(mn0, __shfl_xor_sync(0xffffffffu, mn0, 1));
        mn0 = fmaxf(mn0, __shfl_xor_sync(0xffffffffu, mn0, 2));
        mn1 = fmaxf(mn1, __shfl_xor_sync(0xffffffffu, mn1, 1));
        mn1 = fmaxf(mn1, __shfl_xor_sync(0xffffffffu, mn1, 2));

        const float alpha0 = __expf(m0 - mn0);
        const float alpha1 = __expf(m1 - mn1);
        m0 = mn0; m1 = mn1;

        float sum0 = 0.f, sum1 = 0.f;
        #pragma unroll
        for (int j = 0; j < 8; j++) {
            s[j][0] = __expf(s[j][0] - mn0);
            s[j][1] = __expf(s[j][1] - mn0);
            s[j][2] = __expf(s[j][2] - mn1);
            s[j][3] = __expf(s[j][3] - mn1);
            sum0 += s[j][0] + s[j][1];
            sum1 += s[j][2] + s[j][3];
        }
        sum0 += __shfl_xor_sync(0xffffffffu, sum0, 1);
        sum0 += __shfl_xor_sync(0xffffffffu, sum0, 2);
        sum1 += __shfl_xor_sync(0xffffffffu, sum1, 1);
        sum1 += __shfl_xor_sync(0xffffffffu, sum1, 2);
        l0 = l0 * alpha0 + sum0;
        l1 = l1 * alpha1 + sum1;

        #pragma unroll
        for (int i = 0; i < 24; i++) {
            acc_o[i][0] *= alpha0; acc_o[i][1] *= alpha0;
            acc_o[i][2] *= alpha1; acc_o[i][3] *= alpha1;
        }

        #pragma unroll
        for (int kc2 = 0; kc2 < 4; ++kc2) {
            uint32_t af[4];
            af[0] = pack_bf2(s[2 * kc2][0],     s[2 * kc2][1]);
            af[1] = pack_bf2(s[2 * kc2][2],     s[2 * kc2][3]);
            af[2] = pack_bf2(s[2 * kc2 + 1][0], s[2 * kc2 + 1][1]);
            af[3] = pack_bf2(s[2 * kc2 + 1][2], s[2 * kc2 + 1][3]);
            const int krow = kc2 * 16 + (lane & 7) + (((lane >> 3) & 1) << 3);
            #pragma unroll
            for (int g = 0; g < 12; g++) {
                uint32_t bv[4];
                ldsm_x4_t(bv, Vs + sw384(krow, g * 2 + (lane >> 4)));
                mma16816(acc_o[2 * g],     af, &bv[0]);
                mma16816(acc_o[2 * g + 1], af, &bv[2]);
            }
        }
    }

    const float inv0 = 1.0f / l0;
    const float inv1 = 1.0f / l1;
    const size_t coff = ((size_t)(b * S_ + qt * 128 + w * 16 + (lane >> 2))) * HID_ + h * HD_;
    #pragma unroll
    for (int i = 0; i < 24; i++) {
        const int d = i * 8 + qcol0;
        *(uint32_t*)&g_chi[coff + d] = pack_bf2(acc_o[i][0] * inv0, acc_o[i][1] * inv0);
        *(uint32_t*)&g_chi[coff + 8 * HID_ + d] = pack_bf2(acc_o[i][2] * inv1, acc_o[i][3] * inv1);
    }
    #undef FA_LOAD
}

// ---------------- fused LayerNorm + classifier (float4 loads) ----------------
// 288 threads (9 warps); threads 0..191 load one float4 each (768 floats).
__global__ __launch_bounds__(288) void ln_cls_kernel(
    const float* __restrict__ lng, const float* __restrict__ lnb,
    const float* __restrict__ Ws, const float* __restrict__ bs)
{
    __shared__ float sh[HID_];
    __shared__ float red[288];
    const int row = blockIdx.x;
    const float* p = g_h + (size_t)row * HID_;
    const int tid = threadIdx.x;

    float ssum = 0.f;
    if (tid < 192) {
        float4 v = *(const float4*)(p + tid * 4);
        *(float4*)&sh[tid * 4] = v;
        ssum = v.x + v.y + v.z + v.w;
    }
    red[tid] = ssum;
    __syncthreads();
    if (tid < 32) red[tid] += red[tid + 256];
    __syncthreads();
    for (int off = 128; off > 0; off >>= 1) {
        if (tid < off) red[tid] += red[tid + off];
        __syncthreads();
    }
    const float mu = red[0] * (1.0f / HID_);
    __syncthreads();

    float sq = 0.f;
    if (tid < 192) {
        float4 v = *(const float4*)&sh[tid * 4];
        float d0 = v.x - mu, d1 = v.y - mu, d2 = v.z - mu, d3 = v.w - mu;
        sq = d0 * d0 + d1 * d1 + d2 * d2 + d3 * d3;
    }
    red[tid] = sq;
    __syncthreads();
    if (tid < 32) red[tid] += red[tid + 256];
    __syncthreads();
    for (int off = 128; off > 0; off >>= 1) {
        if (tid < off) red[tid] += red[tid + off];
        __syncthreads();
    }
    const float rstd = rsqrtf(red[0] * (1.0f / HID_) + 1e-5f);
    __syncthreads();

    if (tid < 192) {
        float4 v = *(const float4*)&sh[tid * 4];
        float4 g = *(const float4*)(lng + tid * 4);
        float4 bb = *(const float4*)(lnb + tid * 4);
        v.x = (v.x - mu) * rstd * g.x + bb.x;
        v.y = (v.y - mu) * rstd * g.y + bb.y;
        v.z = (v.z - mu) * rstd * g.z + bb.z;
        v.w = (v.w - mu) * rstd * g.w + bb.w;
        *(float4*)&sh[tid * 4] = v;
    }
    __syncthreads();

    const int w = tid >> 5;
    const int lane = tid & 31;
    float a = 0.f;
    for (int d = lane; d < HID_; d += 32)
        a = fmaf(sh[d], Ws[d * NL_ + w], a);
    #pragma unroll
    for (int off = 16; off > 0; off >>= 1)
        a += __shfl_down_sync(0xffffffffu, a, off);
    if (lane == 0)
        g_logits[(size_t)row * NL_ + w] = a + bs[w];
}

// ---------------- entity-bias bump + final write ----------------
__global__ __launch_bounds__(256) void bump_kernel(
    const float* __restrict__ eb, float* __restrict__ out)
{
    int row = blockIdx.x * 256 + threadIdx.x;
    if (row >= M_ROWS) return;
    float add = 0.f;
    if (row & (S_ - 1)) {
        const float* lp = g_logits + (size_t)(row - 1) * NL_;
        int am = 0; float best = lp[0];
        #pragma unroll
        for (int l = 1; l < NL_; l++)
            if (lp[l] > best) { best = lp[l]; am = l; }
        if (am == 1) add = 2.0f * eb[2];
    }
    const float* lc = g_logits + (size_t)row * NL_;
    #pragma unroll
    for (int l = 0; l < NL_; l++)
        out[(size_t)row * NL_ + l] = lc[l] + ((l == 2) ? add : 0.f);
}

// ---------------- launch ----------------
extern "C" void kernel_launch(void* const* d_in, const int* in_sizes, int n_in,
                              void* d_out, int out_size)
{
    const float* x   = (const float*)d_in[0];
    const float* Wq  = (const float*)d_in[1];
    const float* bq  = (const float*)d_in[2];
    const float* Wk  = (const float*)d_in[3];
    const float* bk  = (const float*)d_in[4];
    const float* Wv  = (const float*)d_in[5];
    const float* bv  = (const float*)d_in[6];
    const float* Wo  = (const float*)d_in[7];
    const float* bo  = (const float*)d_in[8];
    const float* lng = (const float*)d_in[9];
    const float* lnb = (const float*)d_in[10];
    const float* Ws  = (const float*)d_in[11];
    const float* bs  = (const float*)d_in[12];
    const float* eb  = (const float*)d_in[13];
    float* out = (float*)d_out;

    __nv_bfloat16 *xhi, *wqkvThi, *woThi, *chi;
    float *gh;
    cudaGetSymbolAddress((void**)&xhi, g_xhi);
    cudaGetSymbolAddress((void**)&wqkvThi, g_wqkvThi);
    cudaGetSymbolAddress((void**)&woThi, g_woThi);
    cudaGetSymbolAddress((void**)&chi, g_chi);
    cudaGetSymbolAddress((void**)&gh, g_h);

    const int SMEM_G  = 3 * 16384;                // 49152, 2 CTAs/SM
    const int SMEM_FA = FA_QSZ + 3 * FA_STAGE;    // 196608, 1 CTA/SM
    cudaFuncSetAttribute(mma_gemm<0>, cudaFuncAttributeMaxDynamicSharedMemorySize, SMEM_G);
    cudaFuncSetAttribute(mma_gemm<1>, cudaFuncAttributeMaxDynamicSharedMemorySize, SMEM_G);
    cudaFuncSetAttribute(flash_attn,  cudaFuncAttributeMaxDynamicSharedMemorySize, SMEM_FA);

    // 1. round x -> bf16
    round4_kernel<<<(M_ROWS * HID_ / 4 + 255) / 256, 256>>>(x, xhi, M_ROWS * HID_ / 4);
    // 2. transpose weights -> bf16
    wtrans_kernel<<<dim3(24, 24, 4), dim3(32, 8)>>>(Wq, Wk, Wv, Wo);
    // 3. QKV projection (1-pass bf16) -> q/k/v bf16
    mma_gemm<0><<<dim3(18, 64, 1), 256, SMEM_G>>>(
        xhi, HID_, wqkvThi, HID_, nullptr, 0, HID_, bq, bk, bv, nullptr);
    // 4. fused attention -> ctx bf16
    flash_attn<<<dim3(4, BH_), 256, SMEM_FA>>>();
    // 5. O projection (1-pass bf16) + bias + fp32 residual -> g_h
    mma_gemm<1><<<dim3(6, 64, 1), 256, SMEM_G>>>(
        chi, HID_, woThi, HID_, gh, HID_, HID_, bo, nullptr, nullptr, x);
    // 6. fused layernorm + classifier -> g_logits
    ln_cls_kernel<<<M_ROWS, 288>>>(lng, lnb, Ws, bs);
    // 7. entity bump + final write
    bump_kernel<<<(M_ROWS + 255) / 256, 256>>>(eb, out);
}

// round 17
// speedup vs baseline: 1.2573x; 1.0043x over previous
#include <cuda_runtime.h>
#include <cuda_bf16.h>
#include <cstdint>
#include <math.h>

// ---------------- problem constants ----------------
#define B_   16
#define S_   512
#define HID_ 768
#define NH_  4
#define HD_  192
#define NL_  9
#define M_ROWS (B_ * S_)   // 8192
#define BH_ (B_ * NH_)     // 64
#define INV_SQRT_D 0.07216878364870323f

// exp(-0.1*k), k=0..5 (dist is integer and clamped)
#define RT0 1.0f
#define RT1 0.9048374180359595f
#define RT2 0.8187307530779818f
#define RT3 0.7408182206817179f
#define RT4 0.6703200460356393f
#define RT5 0.6065306597126334f
__device__ __forceinline__ float rel_tab(int d) {
    return d >= 5 ? RT5 : (d == 0 ? RT0 : d == 1 ? RT1 : d == 2 ? RT2 : d == 3 ? RT3 : RT4);
}

// ---------------- mma / cp.async helpers (sm_80-compatible PTX) ----------------
__device__ __forceinline__ uint32_t smem_to_u32(const void* p) {
    uint32_t a;
    asm("{ .reg .u64 t; cvta.to.shared.u64 t, %1; cvt.u32.u64 %0, t; }" : "=r"(a) : "l"(p));
    return a;
}
__device__ __forceinline__ void ldsm_x4(uint32_t* r, uint32_t addr) {
    asm volatile("ldmatrix.sync.aligned.m8n8.x4.shared.b16 {%0,%1,%2,%3}, [%4];"
        : "=r"(r[0]), "=r"(r[1]), "=r"(r[2]), "=r"(r[3]) : "r"(addr));
}
__device__ __forceinline__ void ldsm_x4_t(uint32_t* r, uint32_t addr) {
    asm volatile("ldmatrix.sync.aligned.m8n8.x4.trans.shared.b16 {%0,%1,%2,%3}, [%4];"
        : "=r"(r[0]), "=r"(r[1]), "=r"(r[2]), "=r"(r[3]) : "r"(addr));
}
__device__ __forceinline__ void mma16816(float* d, const uint32_t* a, const uint32_t* b) {
    asm volatile("mma.sync.aligned.m16n8k16.row.col.f32.bf16.bf16.f32 "
        "{%0,%1,%2,%3}, {%4,%5,%6,%7}, {%8,%9}, {%0,%1,%2,%3};"
        : "+f"(d[0]), "+f"(d[1]), "+f"(d[2]), "+f"(d[3])
        : "r"(a[0]), "r"(a[1]), "r"(a[2]), "r"(a[3]), "r"(b[0]), "r"(b[1]));
}
__device__ __forceinline__ void cp16(uint32_t saddr, const void* g) {
    asm volatile("cp.async.cg.shared.global [%0], [%1], 16;" :: "r"(saddr), "l"(g));
}
#define CP_COMMIT() asm volatile("cp.async.commit_group;" ::: "memory")
#define CP_WAIT1()  asm volatile("cp.async.wait_group 1;" ::: "memory")

// 64-byte rows (4 x 16B chunks)
__device__ __forceinline__ uint32_t sw64(int row, int c16) {
    return (uint32_t)(row * 64 + ((c16 ^ ((row >> 1) & 3)) << 4));
}
// 384-byte rows (24 x 16B chunks): xor low 3 bits of chunk with row&7
__device__ __forceinline__ uint32_t sw384(int row, int c16) {
    return (uint32_t)(row * 384 + ((c16 ^ (row & 7)) << 4));
}

// ---------------- device scratch ----------------
__device__ __nv_bfloat16 g_xhi[M_ROWS * HID_];
__device__ __nv_bfloat16 g_wqkvThi[3 * HID_ * HID_];
__device__ __nv_bfloat16 g_woThi[HID_ * HID_];
__device__ __nv_bfloat16 g_qhi[M_ROWS * HID_];
__device__ __nv_bfloat16 g_khi[M_ROWS * HID_];
__device__ __nv_bfloat16 g_vhi[M_ROWS * HID_];                       // natural [s][d]
__device__ __nv_bfloat16 g_chi[M_ROWS * HID_];
__device__ float         g_h[M_ROWS * HID_];
__device__ float         g_logits[M_ROWS * NL_];

__device__ __forceinline__ uint32_t pack_bf2(float a, float b) {
    __nv_bfloat162 t(__float2bfloat16(a), __float2bfloat16(b));
    return *(uint32_t*)&t;
}

// ---------------- input conversion kernels ----------------
__global__ __launch_bounds__(256) void round4_kernel(
    const float* __restrict__ src, __nv_bfloat16* __restrict__ hi, int n4)
{
    int i = blockIdx.x * 256 + threadIdx.x;
    if (i >= n4) return;
    float4 v = ((const float4*)src)[i];
    __nv_bfloat162 a(__float2bfloat16(v.x), __float2bfloat16(v.y));
    __nv_bfloat162 b(__float2bfloat16(v.z), __float2bfloat16(v.w));
    *(__nv_bfloat162*)(hi + i * 4)     = a;
    *(__nv_bfloat162*)(hi + i * 4 + 2) = b;
}

// weight transpose: z in {0,1,2} -> qkvT, z==3 -> woT (all bf16 hi only)
__global__ void wtrans_kernel(const float* __restrict__ Wq, const float* __restrict__ Wk,
                              const float* __restrict__ Wv, const float* __restrict__ Wo)
{
    __shared__ float tl[32][33];
    const int z = blockIdx.z;
    const float* W = (z == 0) ? Wq : (z == 1) ? Wk : (z == 2) ? Wv : Wo;
    const int n0 = blockIdx.x * 32, k0 = blockIdx.y * 32;
    const int tx = threadIdx.x, ty = threadIdx.y;  // (32,8)
    #pragma unroll
    for (int i = 0; i < 4; i++) {
        int k = ty + i * 8;
        tl[k][tx] = W[(size_t)(k0 + k) * HID_ + n0 + tx];
    }
    __syncthreads();
    #pragma unroll
    for (int i = 0; i < 4; i++) {
        int nloc = ty + i * 8;
        float v = tl[tx][nloc];
        if (z < 3) {
            size_t o = (size_t)(z * HID_ + n0 + nloc) * HID_ + k0 + tx;
            g_wqkvThi[o] = __float2bfloat16(v);
        } else {
            size_t o = (size_t)(n0 + nloc) * HID_ + k0 + tx;
            g_woThi[o] = __float2bfloat16(v);
        }
    }
}

// ---------------- stage loader (cp.async, 64B rows, 256 threads) ----------------
__device__ __forceinline__ void stage_load_g(
    uint32_t sstage,
    const __nv_bfloat16* Ah, const __nv_bfloat16* Bh,
    int lda, int ldb, int tid)
{
    const int row = tid >> 1;
    const int c0  = (tid & 1) * 2;
    const uint32_t s0 = sw64(row, c0);
    const uint32_t s1 = sw64(row, c0 + 1);
    const size_t goA = (size_t)row * lda + c0 * 8;
    const size_t goB = (size_t)row * ldb + c0 * 8;
    cp16(sstage + s0, Ah + goA);
    cp16(sstage + s1, Ah + goA + 8);
    cp16(sstage + 8192 + s0, Bh + goB);
    cp16(sstage + 8192 + s1, Bh + goB + 8);
}

// ---------------- 1-pass bf16 mma.sync GEMM (NT), k-chunk 32, 3-stage -------
// Block 128x128, 8 warps 2x4, warp tile 64x32, 2 CTAs/SM.  (champion config)
// MODE 0: QKV -> q/k/v bf16 (bias fused)   MODE 1: O proj -> fp32 (bias+resid)
template<int MODE>
__global__ __launch_bounds__(256, 2) void mma_gemm(
    const __nv_bfloat16* __restrict__ Ahi, int lda,
    const __nv_bfloat16* __restrict__ Bhi, int ldb,
    float* __restrict__ C, int ldc, int K,
    const float* __restrict__ bb0, const float* __restrict__ bb1,
    const float* __restrict__ bb2, const float* __restrict__ resid)
{
    constexpr int TSZ   = 128 * 64;     // 8192
    constexpr int STAGE = 2 * TSZ;      // 16384

    extern __shared__ char smem[];
    const uint32_t sbase = smem_to_u32(smem);
    const int tid  = threadIdx.x;
    const int lane = tid & 31;
    const int wid  = tid >> 5;
    const int wm   = (wid >> 2) * 64;
    const int wn   = (wid & 3) * 32;

    const int bm = blockIdx.y * 128;
    const int bn = blockIdx.x * 128;

    const __nv_bfloat16* Ah = Ahi + (size_t)bm * lda;
    const __nv_bfloat16* Bh = Bhi + (size_t)bn * ldb;

    float acc[4][4][4];
    #pragma unroll
    for (int i = 0; i < 4; i++)
        #pragma unroll
        for (int j = 0; j < 4; j++)
            #pragma unroll
            for (int u = 0; u < 4; u++) acc[i][j][u] = 0.f;

    const int nt = K >> 5;

    stage_load_g(sbase, Ah, Bh, lda, ldb, tid);
    CP_COMMIT();
    stage_load_g(sbase + STAGE, Ah + 32, Bh + 32, lda, ldb, tid);
    CP_COMMIT();

    for (int t = 0; t < nt; ++t) {
        CP_WAIT1();
        __syncthreads();

        {
            const uint32_t aB = sbase + (t % 3) * STAGE;
            const uint32_t bB = aB + TSZ;
            #pragma unroll
            for (int ks = 0; ks < 2; ++ks) {
                uint32_t ah[4][4];
                const int arow0 = wm + (lane & 15);
                const int ac16  = ks * 2 + (lane >> 4);
                #pragma unroll
                for (int im = 0; im < 4; im++)
                    ldsm_x4(ah[im], aB + sw64(arow0 + im * 16, ac16));
                uint32_t bhf[2][4];
                const int brow0 = wn + (lane & 7) + ((lane >> 4) << 3);
                const int bc16  = ks * 2 + ((lane >> 3) & 1);
                #pragma unroll
                for (int ib = 0; ib < 2; ib++)
                    ldsm_x4(bhf[ib], bB + sw64(brow0 + ib * 16, bc16));
                #pragma unroll
                for (int im = 0; im < 4; im++)
                    #pragma unroll
                    for (int in = 0; in < 4; in++)
                        mma16816(acc[im][in], ah[im], &bhf[in >> 1][(in & 1) * 2]);
            }
        }

        if (t + 2 < nt) {
            stage_load_g(sbase + ((t + 2) % 3) * STAGE,
                         Ah + (t + 2) * 32, Bh + (t + 2) * 32, lda, ldb, tid);
        }
        CP_COMMIT();
    }

    // ---- epilogue ----
    #pragma unroll
    for (int im = 0; im < 4; im++) {
        #pragma unroll
        for (int in = 0; in < 4; in++) {
            const int gm0 = bm + wm + im * 16 + (lane >> 2);
            const int n   = bn + wn + in * 8 + ((lane & 3) << 1);
            float* d = acc[im][in];
            if (MODE == 0) {
                #pragma unroll
                for (int half = 0; half < 2; half++) {
                    int gm = gm0 + half * 8;
                    float v0 = d[half * 2 + 0];
                    float v1 = d[half * 2 + 1];
                    int seg = (n >= 1536) ? 2 : (n >= 768) ? 1 : 0;
                    int col = n - seg * 768;
                    const float* bias = (seg == 0) ? bb0 : (seg == 1) ? bb1 : bb2;
                    v0 += bias[col];
                    v1 += bias[col + 1];
                    size_t o = (size_t)gm * HID_ + col;
                    __nv_bfloat16* dh = (seg == 0) ? &g_qhi[o] : (seg == 1) ? &g_khi[o] : &g_vhi[o];
                    *(__nv_bfloat162*)dh = __nv_bfloat162(__float2bfloat16(v0), __float2bfloat16(v1));
                }
            } else {
                #pragma unroll
                for (int half = 0; half < 2; half++) {
                    int gm = gm0 + half * 8;
                    float2 o;
                    o.x = d[half * 2 + 0] + bb0[n]     + resid[(size_t)gm * HID_ + n];
                    o.y = d[half * 2 + 1] + bb0[n + 1] + resid[(size_t)gm * HID_ + n + 1];
                    *(float2*)(C + (size_t)gm * ldc + n) = o;
                }
            }
        }
    }
}

// ---------------- fused flash attention (static-max softmax) ----------------
// Scores are bounded (~|s| <= few) by construction, so exp(s) without max
// subtraction is safe in fp32. No m-tracking, no alpha rescale, no per-kt
// reductions — l reduced across quads once after the loop.
#define FA_QSZ   49152                    // 128 x 384B
#define FA_KVSZ  24576                    // 64 x 384B
#define FA_STAGE (2 * FA_KVSZ)            // K + V
__global__ __launch_bounds__(256, 1) void flash_attn()
{
    extern __shared__ char smem[];
    const uint32_t sbase = smem_to_u32(smem);
    const uint32_t Qs = sbase;

    const int tid  = threadIdx.x;
    const int lane = tid & 31;
    const int w    = tid >> 5;

    const int qt = blockIdx.x;
    const int bh = blockIdx.y;
    const int b = bh >> 2, h = bh & 3;

    const __nv_bfloat16* Qg = g_qhi + ((size_t)(b * S_ + qt * 128)) * HID_ + h * HD_;
    const __nv_bfloat16* Kg = g_khi + ((size_t)(b * S_)) * HID_ + h * HD_;
    const __nv_bfloat16* Vg = g_vhi + ((size_t)(b * S_)) * HID_ + h * HD_;

    {
        const int row = tid >> 1;
        const int c0  = (tid & 1) * 12;
        #pragma unroll
        for (int j = 0; j < 12; j++)
            cp16(Qs + sw384(row, c0 + j), Qg + (size_t)row * HID_ + (c0 + j) * 8);
    }

    #define FA_LOAD(KT, STG) do { \
        uint32_t sb_ = sbase + FA_QSZ + (STG) * FA_STAGE; \
        const int row_ = tid >> 2; \
        const int c0_  = (tid & 3) * 6; \
        const __nv_bfloat16* Kp = Kg + (size_t)((KT) * 64 + row_) * HID_; \
        const __nv_bfloat16* Vp = Vg + (size_t)((KT) * 64 + row_) * HID_; \
        _Pragma("unroll") \
        for (int j_ = 0; j_ < 6; j_++) { \
            uint32_t so_ = sw384(row_, c0_ + j_); \
            cp16(sb_ + so_,           Kp + (c0_ + j_) * 8); \
            cp16(sb_ + FA_KVSZ + so_, Vp + (c0_ + j_) * 8); \
        } \
    } while (0)

    FA_LOAD(0, 0); CP_COMMIT();
    FA_LOAD(1, 1); CP_COMMIT();

    float acc_o[24][4];
    #pragma unroll
    for (int i = 0; i < 24; i++)
        #pragma unroll
        for (int u = 0; u < 4; u++) acc_o[i][u] = 0.f;
    float l0 = 0.f, l1 = 0.f;     // per-lane partial row sums

    const int qrow0 = qt * 128 + w * 16 + (lane >> 2);
    const int qcol0 = (lane & 3) << 1;

    for (int kt = 0; kt < 8; ++kt) {
        CP_WAIT1();
        __syncthreads();

        if (kt + 2 < 8) FA_LOAD(kt + 2, (kt + 2) % 3);
        CP_COMMIT();

        const uint32_t Ks = sbase + FA_QSZ + (kt % 3) * FA_STAGE;
        const uint32_t Vs = Ks + FA_KVSZ;

        // ---- S = Q K^T ----
        float s[8][4];
        #pragma unroll
        for (int j = 0; j < 8; j++)
            #pragma unroll
            for (int u = 0; u < 4; u++) s[j][u] = 0.f;

        #pragma unroll
        for (int kc = 0; kc < 12; ++kc) {
            uint32_t aq[4];
            ldsm_x4(aq, Qs + sw384(w * 16 + (lane & 15), kc * 2 + (lane >> 4)));
            #pragma unroll
            for (int g = 0; g < 4; g++) {
                uint32_t bk[4];
                ldsm_x4(bk, Ks + sw384(g * 16 + (lane & 7) + ((lane >> 4) << 3),
                                       kc * 2 + ((lane >> 3) & 1)));
                mma16816(s[2 * g],     aq, &bk[0]);
                mma16816(s[2 * g + 1], aq, &bk[2]);
            }
        }

        // ---- bias + exp (no max subtraction; scores bounded) ----
        #pragma unroll
        for (int j = 0; j < 8; j++) {
            const int kc0 = kt * 64 + j * 8 + qcol0;
            int da = qrow0 - kc0;        da = da < 0 ? -da : da;
            int db = qrow0 - (kc0 + 1);  db = db < 0 ? -db : db;
            int dc = qrow0 + 8 - kc0;    dc = dc < 0 ? -dc : dc;
            int dd = qrow0 + 8 - (kc0 + 1); dd = dd < 0 ? -dd : dd;
            s[j][0] = __expf((s[j][0] + rel_tab(da)) * INV_SQRT_D - 0.1f * (float)da);
            s[j][1] = __expf((s[j][1] + rel_tab(db)) * INV_SQRT_D - 0.1f * (float)db);
            s[j][2] = __expf((s[j][2] + rel_tab(dc)) * INV_SQRT_D - 0.1f * (float)dc);
            s[j][3] = __expf((s[j][3] + rel_tab(dd)) * INV_SQRT_D - 0.1f * (float)dd);
            l0 += s[j][0] + s[j][1];
            l1 += s[j][2] + s[j][3];
        }

        // ---- P @ V (no rescale needed) ----
        #pragma unroll
        for (int kc2 = 0; kc2 < 4; ++kc2) {
            uint32_t af[4];
            af[0] = pack_bf2(s[2 * kc2][0],     s[2 * kc2][1]);
            af[1] = pack_bf2(s[2 * kc2][2],     s[2 * kc2][3]);
            af[2] = pack_bf2(s[2 * kc2 + 1][0], s[2 * kc2 + 1][1]);
            af[3] = pack_bf2(s[2 * kc2 + 1][2], s[2 * kc2 + 1][3]);
            const int krow = kc2 * 16 + (lane & 7) + (((lane >> 3) & 1) << 3);
            #pragma unroll
            for (int g = 0; g < 12; g++) {
                uint32_t bv[4];
                ldsm_x4_t(bv, Vs + sw384(krow, g * 2 + (lane >> 4)));
                mma16816(acc_o[2 * g],     af, &bv[0]);
                mma16816(acc_o[2 * g + 1], af, &bv[2]);
            }
        }
    }

    // ---- final row-sum reduction across the quad, then normalize ----
    l0 += __shfl_xor_sync(0xffffffffu, l0, 1);
    l0 += __shfl_xor_sync(0xffffffffu, l0, 2);
    l1 += __shfl_xor_sync(0xffffffffu, l1, 1);
    l1 += __shfl_xor_sync(0xffffffffu, l1, 2);
    const float inv0 = 1.0f / l0;
    const float inv1 = 1.0f / l1;
    const size_t coff = ((size_t)(b * S_ + qt * 128 + w * 16 + (lane >> 2))) * HID_ + h * HD_;
    #pragma unroll
    for (int i = 0; i < 24; i++) {
        const int d = i * 8 + qcol0;
        *(uint32_t*)&g_chi[coff + d] = pack_bf2(acc_o[i][0] * inv0, acc_o[i][1] * inv0);
        *(uint32_t*)&g_chi[coff + 8 * HID_ + d] = pack_bf2(acc_o[i][2] * inv1, acc_o[i][3] * inv1);
    }
    #undef FA_LOAD
}

// ---------------- fused LayerNorm + classifier (float4 loads) ----------------
__global__ __launch_bounds__(288) void ln_cls_kernel(
    const float* __restrict__ lng, const float* __restrict__ lnb,
    const float* __restrict__ Ws, const float* __restrict__ bs)
{
    __shared__ float sh[HID_];
    __shared__ float red[288];
    const int row = blockIdx.x;
    const float* p = g_h + (size_t)row * HID_;
    const int tid = threadIdx.x;

    float ssum = 0.f;
    if (tid < 192) {
        float4 v = *(const float4*)(p + tid * 4);
        *(float4*)&sh[tid * 4] = v;
        ssum = v.x + v.y + v.z + v.w;
    }
    red[tid] = ssum;
    __syncthreads();
    if (tid < 32) red[tid] += red[tid + 256];
    __syncthreads();
    for (int off = 128; off > 0; off >>= 1) {
        if (tid < off) red[tid] += red[tid + off];
        __syncthreads();
    }
    const float mu = red[0] * (1.0f / HID_);
    __syncthreads();

    float sq = 0.f;
    if (tid < 192) {
        float4 v = *(const float4*)&sh[tid * 4];
        float d0 = v.x - mu, d1 = v.y - mu, d2 = v.z - mu, d3 = v.w - mu;
        sq = d0 * d0 + d1 * d1 + d2 * d2 + d3 * d3;
    }
    red[tid] = sq;
    __syncthreads();
    if (tid < 32) red[tid] += red[tid + 256];
    __syncthreads();
    for (int off = 128; off > 0; off >>= 1) {
        if (tid < off) red[tid] += red[tid + off];
        __syncthreads();
    }
    const float rstd = rsqrtf(red[0] * (1.0f / HID_) + 1e-5f);
    __syncthreads();

    if (tid < 192) {
        float4 v = *(const float4*)&sh[tid * 4];
        float4 g = *(const float4*)(lng + tid * 4);
        float4 bb = *(const float4*)(lnb + tid * 4);
        v.x = (v.x - mu) * rstd * g.x + bb.x;
        v.y = (v.y - mu) * rstd * g.y + bb.y;
        v.z = (v.z - mu) * rstd * g.z + bb.z;
        v.w = (v.w - mu) * rstd * g.w + bb.w;
        *(float4*)&sh[tid * 4] = v;
    }
    __syncthreads();

    const int w = tid >> 5;
    const int lane = tid & 31;
    float a = 0.f;
    for (int d = lane; d < HID_; d += 32)
        a = fmaf(sh[d], Ws[d * NL_ + w], a);
    #pragma unroll
    for (int off = 16; off > 0; off >>= 1)
        a += __shfl_down_sync(0xffffffffu, a, off);
    if (lane == 0)
        g_logits[(size_t)row * NL_ + w] = a + bs[w];
}

// ---------------- entity-bias bump + final write ----------------
__global__ __launch_bounds__(256) void bump_kernel(
    const float* __restrict__ eb, float* __restrict__ out)
{
    int row = blockIdx.x * 256 + threadIdx.x;
    if (row >= M_ROWS) return;
    float add = 0.f;
    if (row & (S_ - 1)) {
        const float* lp = g_logits + (size_t)(row - 1) * NL_;
        int am = 0; float best = lp[0];
        #pragma unroll
        for (int l = 1; l < NL_; l++)
            if (lp[l] > best) { best = lp[l]; am = l; }
        if (am == 1) add = 2.0f * eb[2];
    }
    const float* lc = g_logits + (size_t)row * NL_;
    #pragma unroll
    for (int l = 0; l < NL_; l++)
        out[(size_t)row * NL_ + l] = lc[l] + ((l == 2) ? add : 0.f);
}

// ---------------- launch ----------------
extern "C" void kernel_launch(void* const* d_in, const int* in_sizes, int n_in,
                              void* d_out, int out_size)
{
    const float* x   = (const float*)d_in[0];
    const float* Wq  = (const float*)d_in[1];
    const float* bq  = (const float*)d_in[2];
    const float* Wk  = (const float*)d_in[3];
    const float* bk  = (const float*)d_in[4];
    const float* Wv  = (const float*)d_in[5];
    const float* bv  = (const float*)d_in[6];
    const float* Wo  = (const float*)d_in[7];
    const float* bo  = (const float*)d_in[8];
    const float* lng = (const float*)d_in[9];
    const float* lnb = (const float*)d_in[10];
    const float* Ws  = (const float*)d_in[11];
    const float* bs  = (const float*)d_in[12];
    const float* eb  = (const float*)d_in[13];
    float* out = (float*)d_out;

    __nv_bfloat16 *xhi, *wqkvThi, *woThi, *chi;
    float *gh;
    cudaGetSymbolAddress((void**)&xhi, g_xhi);
    cudaGetSymbolAddress((void**)&wqkvThi, g_wqkvThi);
    cudaGetSymbolAddress((void**)&woThi, g_woThi);
    cudaGetSymbolAddress((void**)&chi, g_chi);
    cudaGetSymbolAddress((void**)&gh, g_h);

    const int SMEM_G  = 3 * 16384;                // 49152, 2 CTAs/SM
    const int SMEM_FA = FA_QSZ + 3 * FA_STAGE;    // 196608, 1 CTA/SM
    cudaFuncSetAttribute(mma_gemm<0>, cudaFuncAttributeMaxDynamicSharedMemorySize, SMEM_G);
    cudaFuncSetAttribute(mma_gemm<1>, cudaFuncAttributeMaxDynamicSharedMemorySize, SMEM_G);
    cudaFuncSetAttribute(flash_attn,  cudaFuncAttributeMaxDynamicSharedMemorySize, SMEM_FA);

    // 1. round x -> bf16
    round4_kernel<<<(M_ROWS * HID_ / 4 + 255) / 256, 256>>>(x, xhi, M_ROWS * HID_ / 4);
    // 2. transpose weights -> bf16
    wtrans_kernel<<<dim3(24, 24, 4), dim3(32, 8)>>>(Wq, Wk, Wv, Wo);
    // 3. QKV projection (1-pass bf16) -> q/k/v bf16
    mma_gemm<0><<<dim3(18, 64, 1), 256, SMEM_G>>>(
        xhi, HID_, wqkvThi, HID_, nullptr, 0, HID_, bq, bk, bv, nullptr);
    // 4. fused attention -> ctx bf16
    flash_attn<<<dim3(4, BH_), 256, SMEM_FA>>>();
    // 5. O projection (1-pass bf16) + bias + fp32 residual -> g_h
    mma_gemm<1><<<dim3(6, 64, 1), 256, SMEM_G>>>(
        chi, HID_, woThi, HID_, gh, HID_, HID_, bo, nullptr, nullptr, x);
    // 6. fused layernorm + classifier -> g_logits
    ln_cls_kernel<<<M_ROWS, 288>>>(lng, lnb, Ws, bs);
    // 7. entity bump + final write
    bump_kernel<<<(M_ROWS + 255) / 256, 256>>>(eb, out);
}